// round 2
// baseline (speedup 1.0000x reference)
#include <cuda_runtime.h>
#include <math.h>

// FLC pooling: out = Re[ ifft2( centered-crop( fftshift(fft2(x, fwd)) ), fwd ) ]
// Reduced analytically to a real separable 113-tap convolution + rank-1 correction.
//
// a[d] = (1/224) * sum_{k=-56}^{55} e^{2pi i k d / 224}
//   a[0] = 1/2 ; a[even d != 0] = 0
//   a[odd d]  = eps(d) * (cot(pi d/224) - i)/224,  eps = +1 if d%4==1 else -1
// Imag parts collapse to: out[m,n] = out1[m,n] - (-1)^(m+n) * C / 224^2
//   C = sum_{h odd, w odd} sigma(h) sigma(w) x[h,w], sigma(+1 if %4==1 else -1)

#define NIMG 1024          // 16*64
#define HH   224
#define HO   112

__device__ float g_rodd[112];               // Re a[2i+1]
__device__ float g_C[NIMG];                 // per-image correction scalar
__device__ float g_T[(size_t)NIMG * HH * HO]; // stage-1 intermediate [img][h][n]

__global__ void init_coef_kernel() {
    int i = threadIdx.x;
    if (i < 112) {
        int d = 2 * i + 1;
        double th = 3.14159265358979323846 * (double)d / 224.0;
        double c  = cos(th) / sin(th);
        double eps = (i & 1) ? -1.0 : 1.0;   // d%4==1 <=> i even
        g_rodd[i] = (float)(eps * c / 224.0);
    }
}

__global__ __launch_bounds__(256) void compute_C_kernel(const float* __restrict__ x) {
    int img = blockIdx.x;
    const float* xi = x + (size_t)img * HH * HH;
    float s = 0.f;
    for (int i = threadIdx.x; i < 112 * 112; i += 256) {
        int a = i / 112, b = i % 112;
        float v = xi[(2 * a + 1) * HH + (2 * b + 1)];
        s += ((a + b) & 1) ? -v : v;
    }
    __shared__ float red[256];
    red[threadIdx.x] = s;
    __syncthreads();
    for (int st = 128; st > 0; st >>= 1) {
        if (threadIdx.x < st) red[threadIdx.x] += red[threadIdx.x + st];
        __syncthreads();
    }
    if (threadIdx.x == 0) g_C[img] = red[0];
}

// ---------------- Stage 1: row convolution  T[R][n] = conv_w(x[R][:]) -------
// block = 32 rows; blockDim (32,4); thread tile = 8 rows x 4 n.
#define ROWS1 32
__global__ __launch_bounds__(128) void stage1_kernel(const float* __restrict__ x) {
    __shared__ float xs[ROWS1 * HH];   // 28 KB
    __shared__ float rs2[256];         // duplicated rodd table, zero-padded
    int tx = threadIdx.x, ty = threadIdx.y;
    int tid = ty * 32 + tx;

    for (int i = tid; i < 256; i += 128)
        rs2[i] = (i < 224) ? g_rodd[(i >= 112) ? (i - 112) : i] : 0.f;

    size_t rowbase = (size_t)blockIdx.x * ROWS1;   // = img*224 + h0 (never crosses image)
    const float* src = x + rowbase * HH;
    for (int i = tid; i < ROWS1 * HH; i += 128) xs[i] = src[i];
    __syncthreads();

    const float* myrow = &xs[ty * 8 * HH];

    float acc[8][4];
    #pragma unroll
    for (int k = 0; k < 4; k++) {
        int n = tx + 32 * k;
        int ne = (n < 112) ? n : 111;
        #pragma unroll
        for (int rr = 0; rr < 8; rr++)
            acc[rr][k] = 0.5f * myrow[rr * HH + 2 * ne];
    }

    #pragma unroll 4
    for (int j = 0; j < 112; j++) {
        float cf[4];
        #pragma unroll
        for (int k = 0; k < 4; k++) cf[k] = rs2[tx + 32 * k + 111 - j];
        float xv[8];
        #pragma unroll
        for (int rr = 0; rr < 8; rr++) xv[rr] = myrow[rr * HH + 2 * j + 1];
        #pragma unroll
        for (int rr = 0; rr < 8; rr++)
            #pragma unroll
            for (int k = 0; k < 4; k++)
                acc[rr][k] += cf[k] * xv[rr];
    }

    #pragma unroll
    for (int k = 0; k < 4; k++) {
        int n = tx + 32 * k;
        if (n < 112) {
            #pragma unroll
            for (int rr = 0; rr < 8; rr++)
                g_T[(rowbase + ty * 8 + rr) * HO + n] = acc[rr][k];
        }
    }
}

// ---------------- Stage 2: column convolution + correction ------------------
// block = one image; dynamic smem: Todd[112][112] + rs2[256] = 51200 B
__global__ __launch_bounds__(128) void stage2_kernel(float* __restrict__ out) {
    extern __shared__ float sm[];
    float* sTodd = sm;            // [112*112]
    float* rs2   = sm + 112 * 112;

    int tx = threadIdx.x, ty = threadIdx.y;
    int tid = ty * 32 + tx;
    int img = blockIdx.x;
    const float* Timg = g_T + (size_t)img * HH * HO;

    for (int i = tid; i < 256; i += 128)
        rs2[i] = (i < 224) ? g_rodd[(i >= 112) ? (i - 112) : i] : 0.f;
    for (int i = tid; i < 112 * 112; i += 128) {
        int j = i / 112, n = i % 112;
        sTodd[i] = Timg[(2 * j + 1) * HO + n];
    }
    __syncthreads();

    float corr = g_C[img] * (1.0f / 50176.0f);

    int nn[4], ne[4];
    #pragma unroll
    for (int k = 0; k < 4; k++) {
        nn[k] = tx + 32 * k;
        ne[k] = (nn[k] < 112) ? nn[k] : 111;
    }

    for (int p = 0; p < 4; p++) {            // m = ty*28 + p*7 + rr, rr<7
        int mbase = ty * 28 + p * 7;
        float acc[7][4];
        #pragma unroll
        for (int rr = 0; rr < 7; rr++) {
            int m = mbase + rr;
            #pragma unroll
            for (int k = 0; k < 4; k++)
                acc[rr][k] = 0.5f * Timg[(2 * m) * HO + ne[k]];
        }
        #pragma unroll 4
        for (int j = 0; j < 112; j++) {
            float tv[4];
            #pragma unroll
            for (int k = 0; k < 4; k++) tv[k] = sTodd[j * 112 + ne[k]];
            float cf[7];
            #pragma unroll
            for (int rr = 0; rr < 7; rr++) cf[rr] = rs2[mbase + rr + 111 - j];
            #pragma unroll
            for (int rr = 0; rr < 7; rr++)
                #pragma unroll
                for (int k = 0; k < 4; k++)
                    acc[rr][k] += cf[rr] * tv[k];
        }
        #pragma unroll
        for (int rr = 0; rr < 7; rr++) {
            int m = mbase + rr;
            #pragma unroll
            for (int k = 0; k < 4; k++) {
                if (nn[k] < 112) {
                    float v = acc[rr][k] - (((m + nn[k]) & 1) ? -corr : corr);
                    out[(size_t)img * HO * HO + m * HO + nn[k]] = v;
                }
            }
        }
    }
}

extern "C" void kernel_launch(void* const* d_in, const int* in_sizes, int n_in,
                              void* d_out, int out_size) {
    (void)in_sizes; (void)n_in; (void)out_size;
    const float* x = (const float*)d_in[0];
    float* out = (float*)d_out;

    static const int SMEM2 = (112 * 112 + 256) * 4;  // 51200 B
    cudaFuncSetAttribute(stage2_kernel,
                         cudaFuncAttributeMaxDynamicSharedMemorySize, SMEM2);

    init_coef_kernel<<<1, 128>>>();
    compute_C_kernel<<<NIMG, 256>>>(x);
    stage1_kernel<<<NIMG * HH / ROWS1, dim3(32, 4)>>>(x);
    stage2_kernel<<<NIMG, dim3(32, 4), SMEM2>>>(out);
}

// round 5
// speedup vs baseline: 1.1006x; 1.1006x over previous
#include <cuda_runtime.h>
#include <cuda_bf16.h>
#include <cstdint>
#include <math.h>

// FLC pooling = two K=112 bf16-split HMMA GEMMs vs fixed Dirichlet odd-tap
// matrix R[112][112] + 0.5*diagonal term + rank-1 imaginary correction.
//   stage1: T[r][n]   = 0.5*x[r][2n]   + sum_j x[r][2j+1] * R[n][j]
//   stage2: out[m][n] = 0.5*T[2m][n]   + sum_j R[m][j] * Todd[j][n]
//                       - (-1)^(m+n) * C_img / 224^2
//   C_img = sum_{h,w odd} (-1)^(a+b) x[2a+1][2b+1]
// bf16 split per operand: P=Ph+Pl; accumulate AhBh + AhBl + AlBh in fp32.

#define HO   112
#define NIMG 1024
#define PADB 240          // smem row stride bytes (120 bf16) -> ldmatrix conflict-free

__device__ float g_C[NIMG];
__device__ __nv_bfloat16 g_Rh[HO * HO], g_Rl[HO * HO];
__device__ __nv_bfloat16 g_Todd_h[(size_t)NIMG * HO * HO];
__device__ __nv_bfloat16 g_Todd_l[(size_t)NIMG * HO * HO];
__device__ float g_Tev[(size_t)NIMG * HO * HO];

// ------------------------------------------------------------------ helpers
__device__ __forceinline__ uint32_t smem_u32(const void* p) {
    uint32_t a;
    asm("{ .reg .u64 t; cvta.to.shared.u64 t, %1; cvt.u32.u64 %0, t; }"
        : "=r"(a) : "l"(p));
    return a;
}
__device__ __forceinline__ void ldx4(uint32_t r[4], uint32_t a) {
    asm volatile("ldmatrix.sync.aligned.m8n8.x4.shared.b16 {%0,%1,%2,%3}, [%4];"
                 : "=r"(r[0]), "=r"(r[1]), "=r"(r[2]), "=r"(r[3]) : "r"(a));
}
__device__ __forceinline__ void ldx2(uint32_t r[2], uint32_t a) {
    asm volatile("ldmatrix.sync.aligned.m8n8.x2.shared.b16 {%0,%1}, [%2];"
                 : "=r"(r[0]), "=r"(r[1]) : "r"(a));
}
__device__ __forceinline__ void ldx4t(uint32_t r[4], uint32_t a) {
    asm volatile("ldmatrix.sync.aligned.m8n8.x4.trans.shared.b16 {%0,%1,%2,%3}, [%4];"
                 : "=r"(r[0]), "=r"(r[1]), "=r"(r[2]), "=r"(r[3]) : "r"(a));
}
__device__ __forceinline__ void ldx2t(uint32_t r[2], uint32_t a) {
    asm volatile("ldmatrix.sync.aligned.m8n8.x2.trans.shared.b16 {%0,%1}, [%2];"
                 : "=r"(r[0]), "=r"(r[1]) : "r"(a));
}
__device__ __forceinline__ void mma16816(float c[4], const uint32_t a[4],
                                         uint32_t b0, uint32_t b1) {
    asm volatile(
        "mma.sync.aligned.m16n8k16.row.col.f32.bf16.bf16.f32 "
        "{%0,%1,%2,%3}, {%4,%5,%6,%7}, {%8,%9}, {%0,%1,%2,%3};"
        : "+f"(c[0]), "+f"(c[1]), "+f"(c[2]), "+f"(c[3])
        : "r"(a[0]), "r"(a[1]), "r"(a[2]), "r"(a[3]), "r"(b0), "r"(b1));
}
__device__ __forceinline__ void split2(float v0, float v1, uint32_t& hp, uint32_t& lp) {
    __nv_bfloat16 h0 = __float2bfloat16_rn(v0), h1 = __float2bfloat16_rn(v1);
    __nv_bfloat16 l0 = __float2bfloat16_rn(v0 - __bfloat162float(h0));
    __nv_bfloat16 l1 = __float2bfloat16_rn(v1 - __bfloat162float(h1));
    __nv_bfloat162 hh; hh.x = h0; hh.y = h1;
    __nv_bfloat162 ll; ll.x = l0; ll.y = l1;
    hp = *reinterpret_cast<uint32_t*>(&hh);
    lp = *reinterpret_cast<uint32_t*>(&ll);
}

// ------------------------------------------------------------------ init
__global__ void init_kernel() {
    int idx = blockIdx.x * blockDim.x + threadIdx.x;
    if (idx < NIMG) g_C[idx] = 0.f;
    if (idx < HO * HO) {
        int n = idx / HO, j = idx % HO;
        int i2 = (n + 111 - j) % 112;
        int d = 2 * i2 + 1;
        double th = 3.14159265358979323846 * (double)d / 224.0;
        double eps = (i2 & 1) ? -1.0 : 1.0;
        float c = (float)(eps * (cos(th) / sin(th)) / 224.0);
        __nv_bfloat16 h = __float2bfloat16_rn(c);
        __nv_bfloat16 l = __float2bfloat16_rn(c - __bfloat162float(h));
        g_Rh[idx] = h; g_Rl[idx] = l;
    }
}

// ------------------------------------------------------------------ stage 1
// CTA = 112 image rows (half image). 2048 CTAs, 256 threads (8 warps, 4M x 2N).
__global__ __launch_bounds__(256) void stage1_kernel(const float* __restrict__ x) {
    extern __shared__ char sm[];
    const uint32_t SA_H = 0, SA_L = 26880, SEV = 53760,
                   SR_H = 103936, SR_L = 130816, SRED = 157696;
    uint32_t sb = smem_u32(sm);
    int tid = threadIdx.x, wid = tid >> 5, lane = tid & 31;
    int bx = blockIdx.x, img = bx >> 1, hbase = (bx & 1) * HO;

    // R -> smem (both splits, padded rows)
    {
        const uint4* rh = (const uint4*)g_Rh;
        const uint4* rl = (const uint4*)g_Rl;
        for (int i = tid; i < 1568; i += 256) {
            int row = i / 14, q = i % 14;
            *(uint4*)(sm + SR_H + row * PADB + q * 16) = rh[i];
            *(uint4*)(sm + SR_L + row * PADB + q * 16) = rl[i];
        }
    }

    // X tile -> smem (odd cols split to bf16 A; even cols fp32) + C partial
    float csum = 0.f;
    {
        const float4* xr = (const float4*)(x + ((size_t)img * 224 + hbase) * 224);
        for (int i = tid; i < 6272; i += 256) {
            int r = i / 56, t = i % 56;
            float4 v = xr[(size_t)r * 56 + t];
            *(float2*)(sm + SEV + (r * 112 + 2 * t) * 4) = make_float2(v.x, v.z);
            uint32_t hp, lp; split2(v.y, v.w, hp, lp);
            *(uint32_t*)(sm + SA_H + r * PADB + 4 * t) = hp;
            *(uint32_t*)(sm + SA_L + r * PADB + 4 * t) = lp;
            if ((hbase + r) & 1) {
                int a = (hbase + r) >> 1;
                csum += (a & 1) ? (v.w - v.y) : (v.y - v.w);
            }
        }
    }
    #pragma unroll
    for (int o = 16; o; o >>= 1) csum += __shfl_down_sync(0xffffffffu, csum, o);
    if (lane == 0) ((float*)(sm + SRED))[wid] = csum;
    __syncthreads();
    if (tid == 0) {
        float s = 0.f;
        #pragma unroll
        for (int i = 0; i < 8; i++) s += ((float*)(sm + SRED))[i];
        atomicAdd(&g_C[img], s);
    }

    int wm = wid & 3, wn = wid >> 2, nbase = wn * 56;
    int mb0 = wm * 16, mb1 = (wm < 3) ? (mb0 + 64) : 96;
    uint32_t aoff = (uint32_t)((lane & 15) * PADB + (lane >> 4) * 16);
    uint32_t aA0 = sb + SA_H + mb0 * PADB + aoff;
    uint32_t aA1 = sb + SA_H + mb1 * PADB + aoff;
    uint32_t bA[4];
    #pragma unroll
    for (int p = 0; p < 3; p++) {
        int n = nbase + p * 16 + (lane & 7) + ((lane & 8) ? 8 : 0);
        int j = (lane & 16) ? 8 : 0;
        bA[p] = sb + SR_H + n * PADB + j * 2;
    }
    {
        int n = nbase + 48 + (lane & 7);
        int j = (lane & 8) ? 8 : 0;
        bA[3] = sb + SR_H + n * PADB + j * 2;
    }

    float acc[2][7][4];
    #pragma unroll
    for (int mt = 0; mt < 2; mt++)
        #pragma unroll
        for (int nt = 0; nt < 7; nt++)
            #pragma unroll
            for (int q = 0; q < 4; q++) acc[mt][nt][q] = 0.f;

    #pragma unroll 1
    for (int kk = 0; kk < 7; kk++) {
        uint32_t ko = (uint32_t)kk * 32;
        uint32_t bh0[7], bh1[7], bl0[7], bl1[7];
        #pragma unroll
        for (int p = 0; p < 3; p++) {
            uint32_t r[4];
            ldx4(r, bA[p] + ko);
            bh0[2 * p] = r[0]; bh0[2 * p + 1] = r[1];
            bh1[2 * p] = r[2]; bh1[2 * p + 1] = r[3];
            ldx4(r, bA[p] + ko + (SR_L - SR_H));
            bl0[2 * p] = r[0]; bl0[2 * p + 1] = r[1];
            bl1[2 * p] = r[2]; bl1[2 * p + 1] = r[3];
        }
        {
            uint32_t r[2];
            ldx2(r, bA[3] + ko);                 bh0[6] = r[0]; bh1[6] = r[1];
            ldx2(r, bA[3] + ko + (SR_L - SR_H)); bl0[6] = r[0]; bl1[6] = r[1];
        }
        uint32_t ah[4], al[4];
        ldx4(ah, aA0 + ko); ldx4(al, aA0 + ko + (SA_L - SA_H));
        #pragma unroll
        for (int nt = 0; nt < 7; nt++) {
            mma16816(acc[0][nt], ah, bh0[nt], bh1[nt]);
            mma16816(acc[0][nt], ah, bl0[nt], bl1[nt]);
            mma16816(acc[0][nt], al, bh0[nt], bh1[nt]);
        }
        ldx4(ah, aA1 + ko); ldx4(al, aA1 + ko + (SA_L - SA_H));
        #pragma unroll
        for (int nt = 0; nt < 7; nt++) {
            mma16816(acc[1][nt], ah, bh0[nt], bh1[nt]);
            mma16816(acc[1][nt], ah, bl0[nt], bl1[nt]);
            mma16816(acc[1][nt], al, bh0[nt], bh1[nt]);
        }
    }

    // epilogue: + 0.5*even, split-route to Todd (bf16 h/l) or Tev (fp32)
    const float* ev = (const float*)(sm + SEV);
    #pragma unroll
    for (int mt = 0; mt < 2; mt++) {
        if (mt == 1 && wm == 3) break;
        int mb = mt ? mb1 : mb0;
        int rlo = mb + (lane >> 2), rhi = rlo + 8;
        #pragma unroll
        for (int nt = 0; nt < 7; nt++) {
            int n = nbase + nt * 8 + 2 * (lane & 3);
            float v0 = acc[mt][nt][0] + 0.5f * ev[rlo * 112 + n];
            float v1 = acc[mt][nt][1] + 0.5f * ev[rlo * 112 + n + 1];
            float v2 = acc[mt][nt][2] + 0.5f * ev[rhi * 112 + n];
            float v3 = acc[mt][nt][3] + 0.5f * ev[rhi * 112 + n + 1];
            #pragma unroll
            for (int hf = 0; hf < 2; hf++) {
                int h = hbase + (hf ? rhi : rlo);
                float a0 = hf ? v2 : v0, a1 = hf ? v3 : v1;
                size_t base = ((size_t)img * HO + (h >> 1)) * HO + n;
                if (h & 1) {
                    uint32_t hp, lp; split2(a0, a1, hp, lp);
                    *(uint32_t*)&g_Todd_h[base] = hp;
                    *(uint32_t*)&g_Todd_l[base] = lp;
                } else {
                    *(float2*)&g_Tev[base] = make_float2(a0, a1);
                }
            }
        }
    }
}

// ------------------------------------------------------------------ stage 2
// CTA = one image. 1024 CTAs, 256 threads, same warp tiling.
__global__ __launch_bounds__(256) void stage2_kernel(float* __restrict__ out) {
    extern __shared__ char sm[];
    const uint32_t ST_H = 0, ST_L = 26880, SR_H = 53760, SR_L = 80640;
    uint32_t sb = smem_u32(sm);
    int tid = threadIdx.x, wid = tid >> 5, lane = tid & 31;
    int img = blockIdx.x;

    {
        const uint4* rh = (const uint4*)g_Rh;
        const uint4* rl = (const uint4*)g_Rl;
        const uint4* th = (const uint4*)(g_Todd_h + (size_t)img * HO * HO);
        const uint4* tl = (const uint4*)(g_Todd_l + (size_t)img * HO * HO);
        for (int i = tid; i < 1568; i += 256) {
            int row = i / 14, q = i % 14;
            uint32_t o = row * PADB + q * 16;
            *(uint4*)(sm + SR_H + o) = rh[i];
            *(uint4*)(sm + SR_L + o) = rl[i];
            *(uint4*)(sm + ST_H + o) = th[i];
            *(uint4*)(sm + ST_L + o) = tl[i];
        }
    }
    __syncthreads();

    float corr = g_C[img] * (1.0f / 50176.0f);

    int wm = wid & 3, wn = wid >> 2, nbase = wn * 56;
    int mb0 = wm * 16, mb1 = (wm < 3) ? (mb0 + 64) : 96;
    uint32_t aoff = (uint32_t)((lane & 15) * PADB + (lane >> 4) * 16);
    uint32_t aA0 = sb + SR_H + mb0 * PADB + aoff;
    uint32_t aA1 = sb + SR_H + mb1 * PADB + aoff;
    uint32_t bA[4];
    #pragma unroll
    for (int p = 0; p < 3; p++) {
        int j = (lane & 7) + ((lane & 8) ? 8 : 0);
        int n = nbase + p * 16 + ((lane & 16) ? 8 : 0);
        bA[p] = sb + ST_H + j * PADB + n * 2;
    }
    {
        int j = lane & 15;
        bA[3] = sb + ST_H + j * PADB + (nbase + 48) * 2;
    }

    float acc[2][7][4];
    #pragma unroll
    for (int mt = 0; mt < 2; mt++)
        #pragma unroll
        for (int nt = 0; nt < 7; nt++)
            #pragma unroll
            for (int q = 0; q < 4; q++) acc[mt][nt][q] = 0.f;

    #pragma unroll 1
    for (int kk = 0; kk < 7; kk++) {
        uint32_t koA = (uint32_t)kk * 32;
        uint32_t koB = (uint32_t)kk * 16 * PADB;
        uint32_t bh0[7], bh1[7], bl0[7], bl1[7];
        #pragma unroll
        for (int p = 0; p < 3; p++) {
            uint32_t r[4];
            ldx4t(r, bA[p] + koB);
            bh0[2 * p] = r[0]; bh1[2 * p] = r[1];
            bh0[2 * p + 1] = r[2]; bh1[2 * p + 1] = r[3];
            ldx4t(r, bA[p] + koB + (ST_L - ST_H));
            bl0[2 * p] = r[0]; bl1[2 * p] = r[1];
            bl0[2 * p + 1] = r[2]; bl1[2 * p + 1] = r[3];
        }
        {
            uint32_t r[2];
            ldx2t(r, bA[3] + koB);                 bh0[6] = r[0]; bh1[6] = r[1];
            ldx2t(r, bA[3] + koB + (ST_L - ST_H)); bl0[6] = r[0]; bl1[6] = r[1];
        }
        uint32_t ah[4], al[4];
        ldx4(ah, aA0 + koA); ldx4(al, aA0 + koA + (SR_L - SR_H));
        #pragma unroll
        for (int nt = 0; nt < 7; nt++) {
            mma16816(acc[0][nt], ah, bh0[nt], bh1[nt]);
            mma16816(acc[0][nt], ah, bl0[nt], bl1[nt]);
            mma16816(acc[0][nt], al, bh0[nt], bh1[nt]);
        }
        ldx4(ah, aA1 + koA); ldx4(al, aA1 + koA + (SR_L - SR_H));
        #pragma unroll
        for (int nt = 0; nt < 7; nt++) {
            mma16816(acc[1][nt], ah, bh0[nt], bh1[nt]);
            mma16816(acc[1][nt], ah, bl0[nt], bl1[nt]);
            mma16816(acc[1][nt], al, bh0[nt], bh1[nt]);
        }
    }

    // epilogue: + 0.5*Tev - sign*corr, write out
    #pragma unroll
    for (int mt = 0; mt < 2; mt++) {
        if (mt == 1 && wm == 3) break;
        int mb = mt ? mb1 : mb0;
        int mlo = mb + (lane >> 2), mhi = mlo + 8;
        #pragma unroll
        for (int nt = 0; nt < 7; nt++) {
            int n = nbase + nt * 8 + 2 * (lane & 3);
            #pragma unroll
            for (int hf = 0; hf < 2; hf++) {
                int m = hf ? mhi : mlo;
                size_t base = ((size_t)img * HO + m) * HO + n;
                float2 te = *(const float2*)&g_Tev[base];
                float v0 = acc[mt][nt][hf ? 2 : 0] + 0.5f * te.x;
                float v1 = acc[mt][nt][hf ? 3 : 1] + 0.5f * te.y;
                v0 -= ((m + n) & 1) ? -corr : corr;
                v1 -= ((m + n + 1) & 1) ? -corr : corr;
                *(float2*)&out[base] = make_float2(v0, v1);
            }
        }
    }
}

// ------------------------------------------------------------------ launch
extern "C" void kernel_launch(void* const* d_in, const int* in_sizes, int n_in,
                              void* d_out, int out_size) {
    (void)in_sizes; (void)n_in; (void)out_size;
    const float* x = (const float*)d_in[0];
    float* out = (float*)d_out;

    cudaFuncSetAttribute(stage1_kernel,
                         cudaFuncAttributeMaxDynamicSharedMemorySize, 157824);
    cudaFuncSetAttribute(stage2_kernel,
                         cudaFuncAttributeMaxDynamicSharedMemorySize, 107520);

    init_kernel<<<49, 256>>>();
    stage1_kernel<<<NIMG * 2, 256, 157824>>>(x);
    stage2_kernel<<<NIMG, 256, 107520>>>(out);
}

// round 7
// speedup vs baseline: 2.4543x; 2.2300x over previous
#include <cuda_runtime.h>
#include <cuda_fp16.h>
#include <cstdint>
#include <math.h>

// FLC pooling = two K=112 fp16 HMMA GEMMs vs fixed Dirichlet odd-tap matrix
// R[112][112] + 0.5*diagonal term + rank-1 imaginary correction.
//   stage1: T[r][n]   = 0.5*x[r][2n] + sum_j x[r][2j+1] * R[n][j]
//   stage2: out[m][n] = 0.5*T[2m][n] + sum_j R[m][j] * To[j][n]
//                       - (-1)^(m+n) * C_img / 224^2
//   C_img = sum_{a,b} (-1)^(a+b) x[2a+1][2b+1]
// fp16 operands (rounding ~1.2e-4 << 1e-3 tolerance), fp32 accumulate.

#define HO   112
#define NIMG 1024
#define PADB 240          // smem row stride bytes (120 fp16) -> conflict-free ldmatrix

__device__ float g_C[NIMG];
__device__ __half g_R[HO * HO];
__device__ __half g_To[(size_t)NIMG * HO * HO];   // odd-row T (stage2 GEMM B)
__device__ __half g_Te[(size_t)NIMG * HO * HO];   // even-row T (stage2 epilogue)

// ------------------------------------------------------------------ helpers
__device__ __forceinline__ uint32_t smem_u32(const void* p) {
    uint32_t a;
    asm("{ .reg .u64 t; cvta.to.shared.u64 t, %1; cvt.u32.u64 %0, t; }"
        : "=r"(a) : "l"(p));
    return a;
}
__device__ __forceinline__ void ldx4(uint32_t r[4], uint32_t a) {
    asm volatile("ldmatrix.sync.aligned.m8n8.x4.shared.b16 {%0,%1,%2,%3}, [%4];"
                 : "=r"(r[0]), "=r"(r[1]), "=r"(r[2]), "=r"(r[3]) : "r"(a));
}
__device__ __forceinline__ void ldx2(uint32_t r[2], uint32_t a) {
    asm volatile("ldmatrix.sync.aligned.m8n8.x2.shared.b16 {%0,%1}, [%2];"
                 : "=r"(r[0]), "=r"(r[1]) : "r"(a));
}
__device__ __forceinline__ void ldx4t(uint32_t r[4], uint32_t a) {
    asm volatile("ldmatrix.sync.aligned.m8n8.x4.trans.shared.b16 {%0,%1,%2,%3}, [%4];"
                 : "=r"(r[0]), "=r"(r[1]), "=r"(r[2]), "=r"(r[3]) : "r"(a));
}
__device__ __forceinline__ void ldx2t(uint32_t r[2], uint32_t a) {
    asm volatile("ldmatrix.sync.aligned.m8n8.x2.trans.shared.b16 {%0,%1}, [%2];"
                 : "=r"(r[0]), "=r"(r[1]) : "r"(a));
}
__device__ __forceinline__ void mma16816(float c[4], const uint32_t a[4],
                                         uint32_t b0, uint32_t b1) {
    asm volatile(
        "mma.sync.aligned.m16n8k16.row.col.f32.f16.f16.f32 "
        "{%0,%1,%2,%3}, {%4,%5,%6,%7}, {%8,%9}, {%0,%1,%2,%3};"
        : "+f"(c[0]), "+f"(c[1]), "+f"(c[2]), "+f"(c[3])
        : "r"(a[0]), "r"(a[1]), "r"(a[2]), "r"(a[3]), "r"(b0), "r"(b1));
}
__device__ __forceinline__ uint32_t pk2(float a, float b) {
    __half2 h = __floats2half2_rn(a, b);
    return *reinterpret_cast<uint32_t*>(&h);
}

// ------------------------------------------------------------------ init
__global__ void init_kernel() {
    int idx = blockIdx.x * blockDim.x + threadIdx.x;
    if (idx < NIMG) g_C[idx] = 0.f;
    if (idx < HO * HO) {
        int n = idx / HO, j = idx % HO;
        int i2 = (n + 111 - j) % 112;
        int d = 2 * i2 + 1;
        float th = 3.14159265358979323846f * (float)d / 224.0f;
        float eps = (i2 & 1) ? -1.0f : 1.0f;
        float c = eps * (cosf(th) / sinf(th)) / 224.0f;
        g_R[idx] = __float2half_rn(c);
    }
}

// ------------------------------------------------------------------ stage 1
// CTA = 112 image rows (half image). 2048 CTAs, 256 threads (8 warps, 4M x 2N).
__global__ __launch_bounds__(256) void stage1_kernel(const float* __restrict__ x) {
    extern __shared__ char sm[];
    const uint32_t SA = 0, SR = 26880, SRED = 53760;   // total 53888
    uint32_t sb = smem_u32(sm);
    int tid = threadIdx.x, wid = tid >> 5, lane = tid & 31;
    int bx = blockIdx.x, img = bx >> 1, hbase = (bx & 1) * HO;

    // R -> smem (padded rows: 112 rows x 14 uint4)
    {
        const uint4* rr = (const uint4*)g_R;
        for (int i = tid; i < 1568; i += 256) {
            int row = i / 14, q = i % 14;
            *(uint4*)(sm + SR + row * PADB + q * 16) = rr[i];
        }
    }

    // X tile odd columns -> fp16 smem A; fused C partial-reduction
    float csum = 0.f;
    {
        const float4* xr = (const float4*)(x + ((size_t)img * 224 + hbase) * 224);
        for (int i = tid; i < 6272; i += 256) {
            int r = i / 56, t = i % 56;
            float4 v = xr[(size_t)r * 56 + t];
            *(uint32_t*)(sm + SA + r * PADB + 4 * t) = pk2(v.y, v.w);
            if ((hbase + r) & 1) {
                int a = (hbase + r) >> 1;
                csum += (a & 1) ? (v.w - v.y) : (v.y - v.w);
            }
        }
    }
    #pragma unroll
    for (int o = 16; o; o >>= 1) csum += __shfl_down_sync(0xffffffffu, csum, o);
    if (lane == 0) ((float*)(sm + SRED))[wid] = csum;
    __syncthreads();
    if (tid == 0) {
        float s = 0.f;
        #pragma unroll
        for (int i = 0; i < 8; i++) s += ((float*)(sm + SRED))[i];
        atomicAdd(&g_C[img], s);
    }

    int wm = wid & 3, wn = wid >> 2, nbase = wn * 56;
    int mb0 = wm * 16, mb1 = (wm < 3) ? (mb0 + 64) : 96;
    uint32_t aoff = (uint32_t)((lane & 15) * PADB + (lane >> 4) * 16);
    uint32_t aA0 = sb + SA + mb0 * PADB + aoff;
    uint32_t aA1 = sb + SA + mb1 * PADB + aoff;
    uint32_t bA[4];
    #pragma unroll
    for (int p = 0; p < 3; p++) {
        int n = nbase + p * 16 + (lane & 7) + ((lane & 8) ? 8 : 0);
        int j = (lane & 16) ? 8 : 0;
        bA[p] = sb + SR + n * PADB + j * 2;
    }
    {
        int n = nbase + 48 + (lane & 7);
        int j = (lane & 8) ? 8 : 0;
        bA[3] = sb + SR + n * PADB + j * 2;
    }

    float acc[2][7][4];
    #pragma unroll
    for (int mt = 0; mt < 2; mt++)
        #pragma unroll
        for (int nt = 0; nt < 7; nt++)
            #pragma unroll
            for (int q = 0; q < 4; q++) acc[mt][nt][q] = 0.f;

    #pragma unroll 1
    for (int kk = 0; kk < 7; kk++) {
        uint32_t ko = (uint32_t)kk * 32;
        uint32_t b0[7], b1[7];
        #pragma unroll
        for (int p = 0; p < 3; p++) {
            uint32_t r[4];
            ldx4(r, bA[p] + ko);
            b0[2 * p] = r[0]; b0[2 * p + 1] = r[1];
            b1[2 * p] = r[2]; b1[2 * p + 1] = r[3];
        }
        {
            uint32_t r[2];
            ldx2(r, bA[3] + ko);
            b0[6] = r[0]; b1[6] = r[1];
        }
        uint32_t a0[4], a1[4];
        ldx4(a0, aA0 + ko);
        ldx4(a1, aA1 + ko);
        #pragma unroll
        for (int nt = 0; nt < 7; nt++) {
            mma16816(acc[0][nt], a0, b0[nt], b1[nt]);
            mma16816(acc[1][nt], a1, b0[nt], b1[nt]);
        }
    }

    // epilogue: + 0.5*x[r][2n] (L2-hot global), route odd/even rows -> To/Te
    const float* xim = x + ((size_t)img * 224 + hbase) * 224;
    #pragma unroll
    for (int mt = 0; mt < 2; mt++) {
        if (mt == 1 && wm == 3) break;
        int mb = mt ? mb1 : mb0;
        int rlo = mb + (lane >> 2), rhi = rlo + 8;
        #pragma unroll
        for (int nt = 0; nt < 7; nt++) {
            int n = nbase + nt * 8 + 2 * (lane & 3);
            float v0 = acc[mt][nt][0] + 0.5f * __ldg(xim + (size_t)rlo * 224 + 2 * n);
            float v1 = acc[mt][nt][1] + 0.5f * __ldg(xim + (size_t)rlo * 224 + 2 * n + 2);
            float v2 = acc[mt][nt][2] + 0.5f * __ldg(xim + (size_t)rhi * 224 + 2 * n);
            float v3 = acc[mt][nt][3] + 0.5f * __ldg(xim + (size_t)rhi * 224 + 2 * n + 2);
            #pragma unroll
            for (int hf = 0; hf < 2; hf++) {
                int h = hbase + (hf ? rhi : rlo);
                uint32_t pv = hf ? pk2(v2, v3) : pk2(v0, v1);
                size_t base = ((size_t)img * HO + (h >> 1)) * HO + n;
                if (h & 1) *(uint32_t*)&g_To[base] = pv;
                else       *(uint32_t*)&g_Te[base] = pv;
            }
        }
    }
}

// ------------------------------------------------------------------ stage 2
// CTA = one image. 1024 CTAs, 256 threads, same warp tiling.
__global__ __launch_bounds__(256) void stage2_kernel(float* __restrict__ out) {
    extern __shared__ char sm[];
    const uint32_t ST = 0, SR = 26880;   // total 53760
    uint32_t sb = smem_u32(sm);
    int tid = threadIdx.x, wid = tid >> 5, lane = tid & 31;
    int img = blockIdx.x;

    {
        const uint4* rr = (const uint4*)g_R;
        const uint4* tt = (const uint4*)(g_To + (size_t)img * HO * HO);
        for (int i = tid; i < 1568; i += 256) {
            int row = i / 14, q = i % 14;
            uint32_t o = row * PADB + q * 16;
            *(uint4*)(sm + SR + o) = rr[i];
            *(uint4*)(sm + ST + o) = tt[i];
        }
    }
    __syncthreads();

    float corr = g_C[img] * (1.0f / 50176.0f);

    int wm = wid & 3, wn = wid >> 2, nbase = wn * 56;
    int mb0 = wm * 16, mb1 = (wm < 3) ? (mb0 + 64) : 96;
    uint32_t aoff = (uint32_t)((lane & 15) * PADB + (lane >> 4) * 16);
    uint32_t aA0 = sb + SR + mb0 * PADB + aoff;
    uint32_t aA1 = sb + SR + mb1 * PADB + aoff;
    uint32_t bA[4];
    #pragma unroll
    for (int p = 0; p < 3; p++) {
        int j = (lane & 7) + ((lane & 8) ? 8 : 0);
        int n = nbase + p * 16 + ((lane & 16) ? 8 : 0);
        bA[p] = sb + ST + j * PADB + n * 2;
    }
    {
        int j = lane & 15;
        bA[3] = sb + ST + j * PADB + (nbase + 48) * 2;
    }

    float acc[2][7][4];
    #pragma unroll
    for (int mt = 0; mt < 2; mt++)
        #pragma unroll
        for (int nt = 0; nt < 7; nt++)
            #pragma unroll
            for (int q = 0; q < 4; q++) acc[mt][nt][q] = 0.f;

    #pragma unroll 1
    for (int kk = 0; kk < 7; kk++) {
        uint32_t koA = (uint32_t)kk * 32;
        uint32_t koB = (uint32_t)kk * 16 * PADB;
        uint32_t b0[7], b1[7];
        #pragma unroll
        for (int p = 0; p < 3; p++) {
            uint32_t r[4];
            ldx4t(r, bA[p] + koB);
            b0[2 * p] = r[0]; b1[2 * p] = r[1];
            b0[2 * p + 1] = r[2]; b1[2 * p + 1] = r[3];
        }
        {
            uint32_t r[2];
            ldx2t(r, bA[3] + koB);
            b0[6] = r[0]; b1[6] = r[1];
        }
        uint32_t a0[4], a1[4];
        ldx4(a0, aA0 + koA);
        ldx4(a1, aA1 + koA);
        #pragma unroll
        for (int nt = 0; nt < 7; nt++) {
            mma16816(acc[0][nt], a0, b0[nt], b1[nt]);
            mma16816(acc[1][nt], a1, b0[nt], b1[nt]);
        }
    }

    // epilogue: + 0.5*Te[m][n] - sign*corr, write fp32 out
    const __half* te = g_Te + (size_t)img * HO * HO;
    #pragma unroll
    for (int mt = 0; mt < 2; mt++) {
        if (mt == 1 && wm == 3) break;
        int mb = mt ? mb1 : mb0;
        int mlo = mb + (lane >> 2), mhi = mlo + 8;
        #pragma unroll
        for (int nt = 0; nt < 7; nt++) {
            int n = nbase + nt * 8 + 2 * (lane & 3);
            #pragma unroll
            for (int hf = 0; hf < 2; hf++) {
                int m = hf ? mhi : mlo;
                size_t base = ((size_t)m) * HO + n;
                uint32_t tp = *(const uint32_t*)&te[base];
                __half2 th = *reinterpret_cast<__half2*>(&tp);
                float v0 = acc[mt][nt][hf ? 2 : 0] + 0.5f * __half2float(th.x);
                float v1 = acc[mt][nt][hf ? 3 : 1] + 0.5f * __half2float(th.y);
                v0 -= ((m + n) & 1) ? -corr : corr;
                v1 -= ((m + n + 1) & 1) ? -corr : corr;
                *(float2*)&out[(size_t)img * HO * HO + base] = make_float2(v0, v1);
            }
        }
    }
}

// ------------------------------------------------------------------ launch
extern "C" void kernel_launch(void* const* d_in, const int* in_sizes, int n_in,
                              void* d_out, int out_size) {
    (void)in_sizes; (void)n_in; (void)out_size;
    const float* x = (const float*)d_in[0];
    float* out = (float*)d_out;

    cudaFuncSetAttribute(stage1_kernel,
                         cudaFuncAttributeMaxDynamicSharedMemorySize, 53888);
    cudaFuncSetAttribute(stage2_kernel,
                         cudaFuncAttributeMaxDynamicSharedMemorySize, 53760);

    init_kernel<<<49, 256>>>();
    stage1_kernel<<<NIMG * 2, 256, 53888>>>(x);
    stage2_kernel<<<NIMG, 256, 53760>>>(out);
}

// round 10
// speedup vs baseline: 3.0673x; 1.2498x over previous
#include <cuda_runtime.h>
#include <cuda_fp16.h>
#include <cstdint>
#include <math.h>

// FLC pooling, fully fused: one CTA per image.
//   stage1: T[h][n]   = 0.5*x[h][2n] + sum_j x[h][2j+1] * R[n][j]   (h = 0..223)
//   stage2: out[m][n] = 0.5*Te[m][n] + sum_j R[m][j] * To[j][n]
//                       - (-1)^(m+n) * C_img / 224^2
//   C_img = sum_{a,b} (-1)^(a+b) x[2a+1][2b+1]
// T kept entirely in shared memory (To = odd h rows, Te = even h rows).
// fp16 operands, fp32 accumulate. R = fixed Dirichlet odd-tap matrix.

#define HO   112
#define NIMG 1024
#define PADB 240          // smem row stride bytes (120 fp16) -> conflict-free ldmatrix

__device__ __half g_R[HO * HO];

// ------------------------------------------------------------------ helpers
__device__ __forceinline__ uint32_t smem_u32(const void* p) {
    uint32_t a;
    asm("{ .reg .u64 t; cvta.to.shared.u64 t, %1; cvt.u32.u64 %0, t; }"
        : "=r"(a) : "l"(p));
    return a;
}
__device__ __forceinline__ void ldx4(uint32_t r[4], uint32_t a) {
    asm volatile("ldmatrix.sync.aligned.m8n8.x4.shared.b16 {%0,%1,%2,%3}, [%4];"
                 : "=r"(r[0]), "=r"(r[1]), "=r"(r[2]), "=r"(r[3]) : "r"(a));
}
__device__ __forceinline__ void ldx2(uint32_t r[2], uint32_t a) {
    asm volatile("ldmatrix.sync.aligned.m8n8.x2.shared.b16 {%0,%1}, [%2];"
                 : "=r"(r[0]), "=r"(r[1]) : "r"(a));
}
__device__ __forceinline__ void ldx4t(uint32_t r[4], uint32_t a) {
    asm volatile("ldmatrix.sync.aligned.m8n8.x4.trans.shared.b16 {%0,%1,%2,%3}, [%4];"
                 : "=r"(r[0]), "=r"(r[1]), "=r"(r[2]), "=r"(r[3]) : "r"(a));
}
__device__ __forceinline__ void ldx2t(uint32_t r[2], uint32_t a) {
    asm volatile("ldmatrix.sync.aligned.m8n8.x2.trans.shared.b16 {%0,%1}, [%2];"
                 : "=r"(r[0]), "=r"(r[1]) : "r"(a));
}
__device__ __forceinline__ void mma16816(float c[4], const uint32_t a[4],
                                         uint32_t b0, uint32_t b1) {
    asm volatile(
        "mma.sync.aligned.m16n8k16.row.col.f32.f16.f16.f32 "
        "{%0,%1,%2,%3}, {%4,%5,%6,%7}, {%8,%9}, {%0,%1,%2,%3};"
        : "+f"(c[0]), "+f"(c[1]), "+f"(c[2]), "+f"(c[3])
        : "r"(a[0]), "r"(a[1]), "r"(a[2]), "r"(a[3]), "r"(b0), "r"(b1));
}
__device__ __forceinline__ uint32_t pk2(float a, float b) {
    __half2 h = __floats2half2_rn(a, b);
    return *reinterpret_cast<uint32_t*>(&h);
}

// ------------------------------------------------------------------ init: R
__global__ void init_kernel() {
    int idx = blockIdx.x * blockDim.x + threadIdx.x;
    if (idx < HO * HO) {
        int n = idx / HO, j = idx % HO;
        int i2 = (n + 111 - j) % 112;
        int d = 2 * i2 + 1;
        float th = 3.14159265358979323846f * (float)d / 224.0f;
        float eps = (i2 & 1) ? -1.0f : 1.0f;
        float c = eps * (cosf(th) / sinf(th)) / 224.0f;
        g_R[idx] = __float2half_rn(c);
    }
}

// ------------------------------------------------------------------ fused
// CTA = one image. 1024 CTAs, 256 threads (8 warps, 4M x 2N warp tiling).
// smem: R 26880 | To 26880 | Te 26880 | A 26880 | red 64  = 107584 B
__global__ __launch_bounds__(256) void fused_kernel(const float* __restrict__ x,
                                                    float* __restrict__ out) {
    extern __shared__ char sm[];
    const uint32_t SR = 0, STo = 26880, STe = 53760, SA = 80640, SRED = 107520;
    uint32_t sb = smem_u32(sm);
    int tid = threadIdx.x, wid = tid >> 5, lane = tid & 31;
    int img = blockIdx.x;

    // R -> smem (112 rows x 14 uint4, padded)
    {
        const uint4* rr = (const uint4*)g_R;
        for (int i = tid; i < 1568; i += 256) {
            int row = i / 14, q = i % 14;
            *(uint4*)(sm + SR + row * PADB + q * 16) = rr[i];
        }
    }

    // warp tiling (shared by both GEMMs)
    int wm = wid & 3, wn = wid >> 2, nbase = wn * 56;
    int mb0 = wm * 16, mb1 = (wm < 3) ? (mb0 + 64) : 96;

    float csum = 0.f;

    // ================= stage 1: two 112-row halves ======================
    #pragma unroll 1
    for (int half = 0; half < 2; half++) {
        int hbase = half * HO;
        if (half) __syncthreads();   // A reuse: all prior ldmatrix reads done

        // x half, odd cols -> fp16 A; fused C partial-reduction
        {
            const float4* xr = (const float4*)(x + ((size_t)img * 224 + hbase) * 224);
            for (int i = tid; i < 6272; i += 256) {
                int r = i / 56, t = i % 56;
                float4 v = xr[(size_t)r * 56 + t];
                *(uint32_t*)(sm + SA + r * PADB + 4 * t) = pk2(v.y, v.w);
                if ((hbase + r) & 1) {
                    int a = (hbase + r) >> 1;
                    csum += (a & 1) ? (v.w - v.y) : (v.y - v.w);
                }
            }
        }
        __syncthreads();

        uint32_t aoff = (uint32_t)((lane & 15) * PADB + (lane >> 4) * 16);
        uint32_t aA0 = sb + SA + mb0 * PADB + aoff;
        uint32_t aA1 = sb + SA + mb1 * PADB + aoff;
        uint32_t bA[4];
        #pragma unroll
        for (int p = 0; p < 3; p++) {
            int n = nbase + p * 16 + (lane & 7) + ((lane & 8) ? 8 : 0);
            int j = (lane & 16) ? 8 : 0;
            bA[p] = sb + SR + n * PADB + j * 2;
        }
        {
            int n = nbase + 48 + (lane & 7);
            int j = (lane & 8) ? 8 : 0;
            bA[3] = sb + SR + n * PADB + j * 2;
        }

        float acc[2][7][4];
        #pragma unroll
        for (int mt = 0; mt < 2; mt++)
            #pragma unroll
            for (int nt = 0; nt < 7; nt++)
                #pragma unroll
                for (int q = 0; q < 4; q++) acc[mt][nt][q] = 0.f;

        #pragma unroll 1
        for (int kk = 0; kk < 7; kk++) {
            uint32_t ko = (uint32_t)kk * 32;
            uint32_t b0[7], b1[7];
            #pragma unroll
            for (int p = 0; p < 3; p++) {
                uint32_t r[4];
                ldx4(r, bA[p] + ko);
                b0[2 * p] = r[0]; b0[2 * p + 1] = r[1];
                b1[2 * p] = r[2]; b1[2 * p + 1] = r[3];
            }
            {
                uint32_t r[2];
                ldx2(r, bA[3] + ko);
                b0[6] = r[0]; b1[6] = r[1];
            }
            uint32_t a0[4], a1[4];
            ldx4(a0, aA0 + ko);
            ldx4(a1, aA1 + ko);
            #pragma unroll
            for (int nt = 0; nt < 7; nt++) {
                mma16816(acc[0][nt], a0, b0[nt], b1[nt]);
                mma16816(acc[1][nt], a1, b0[nt], b1[nt]);
            }
        }

        // epilogue: + 0.5*x[h][2n] (L2-hot), route odd/even h -> To/Te smem
        const float* xim = x + ((size_t)img * 224 + hbase) * 224;
        #pragma unroll
        for (int mt = 0; mt < 2; mt++) {
            if (mt == 1 && wm == 3) break;
            int mb = mt ? mb1 : mb0;
            int rlo = mb + (lane >> 2), rhi = rlo + 8;
            #pragma unroll
            for (int nt = 0; nt < 7; nt++) {
                int n = nbase + nt * 8 + 2 * (lane & 3);
                float v0 = acc[mt][nt][0] + 0.5f * __ldg(xim + (size_t)rlo * 224 + 2 * n);
                float v1 = acc[mt][nt][1] + 0.5f * __ldg(xim + (size_t)rlo * 224 + 2 * n + 2);
                float v2 = acc[mt][nt][2] + 0.5f * __ldg(xim + (size_t)rhi * 224 + 2 * n);
                float v3 = acc[mt][nt][3] + 0.5f * __ldg(xim + (size_t)rhi * 224 + 2 * n + 2);
                #pragma unroll
                for (int hf = 0; hf < 2; hf++) {
                    int h = hbase + (hf ? rhi : rlo);
                    uint32_t pv = hf ? pk2(v2, v3) : pk2(v0, v1);
                    uint32_t off = (uint32_t)((h >> 1) * PADB + 2 * n);
                    if (h & 1) *(uint32_t*)(sm + STo + off) = pv;
                    else       *(uint32_t*)(sm + STe + off) = pv;
                }
            }
        }
    }

    // C reduction -> corr (intra-CTA only)
    #pragma unroll
    for (int o = 16; o; o >>= 1) csum += __shfl_down_sync(0xffffffffu, csum, o);
    if (lane == 0) ((float*)(sm + SRED))[wid] = csum;
    __syncthreads();   // also publishes all To/Te writes
    float corr;
    {
        float s = 0.f;
        #pragma unroll
        for (int i = 0; i < 8; i++) s += ((float*)(sm + SRED))[i];
        corr = s * (1.0f / 50176.0f);
    }

    // ================= stage 2 =========================================
    {
        uint32_t aoff = (uint32_t)((lane & 15) * PADB + (lane >> 4) * 16);
        uint32_t aA0 = sb + SR + mb0 * PADB + aoff;
        uint32_t aA1 = sb + SR + mb1 * PADB + aoff;
        uint32_t bA[4];
        #pragma unroll
        for (int p = 0; p < 3; p++) {
            int j = (lane & 7) + ((lane & 8) ? 8 : 0);
            int n = nbase + p * 16 + ((lane & 16) ? 8 : 0);
            bA[p] = sb + STo + j * PADB + n * 2;
        }
        {
            int j = lane & 15;
            bA[3] = sb + STo + j * PADB + (nbase + 48) * 2;
        }

        float acc[2][7][4];
        #pragma unroll
        for (int mt = 0; mt < 2; mt++)
            #pragma unroll
            for (int nt = 0; nt < 7; nt++)
                #pragma unroll
                for (int q = 0; q < 4; q++) acc[mt][nt][q] = 0.f;

        #pragma unroll 1
        for (int kk = 0; kk < 7; kk++) {
            uint32_t koA = (uint32_t)kk * 32;
            uint32_t koB = (uint32_t)kk * 16 * PADB;
            uint32_t b0[7], b1[7];
            #pragma unroll
            for (int p = 0; p < 3; p++) {
                uint32_t r[4];
                ldx4t(r, bA[p] + koB);
                b0[2 * p] = r[0]; b1[2 * p] = r[1];
                b0[2 * p + 1] = r[2]; b1[2 * p + 1] = r[3];
            }
            {
                uint32_t r[2];
                ldx2t(r, bA[3] + koB);
                b0[6] = r[0]; b1[6] = r[1];
            }
            uint32_t a0[4], a1[4];
            ldx4(a0, aA0 + koA);
            ldx4(a1, aA1 + koA);
            #pragma unroll
            for (int nt = 0; nt < 7; nt++) {
                mma16816(acc[0][nt], a0, b0[nt], b1[nt]);
                mma16816(acc[1][nt], a1, b0[nt], b1[nt]);
            }
        }

        // epilogue: + 0.5*Te[m][n] - sign*corr, write fp32 out
        #pragma unroll
        for (int mt = 0; mt < 2; mt++) {
            if (mt == 1 && wm == 3) break;
            int mb = mt ? mb1 : mb0;
            int mlo = mb + (lane >> 2), mhi = mlo + 8;
            #pragma unroll
            for (int nt = 0; nt < 7; nt++) {
                int n = nbase + nt * 8 + 2 * (lane & 3);
                #pragma unroll
                for (int hf = 0; hf < 2; hf++) {
                    int m = hf ? mhi : mlo;
                    uint32_t tp = *(const uint32_t*)(sm + STe + m * PADB + 2 * n);
                    __half2 th = *reinterpret_cast<__half2*>(&tp);
                    float v0 = acc[mt][nt][hf ? 2 : 0] + 0.5f * __half2float(th.x);
                    float v1 = acc[mt][nt][hf ? 3 : 1] + 0.5f * __half2float(th.y);
                    v0 -= ((m + n) & 1) ? -corr : corr;
                    v1 -= ((m + n + 1) & 1) ? -corr : corr;
                    *(float2*)&out[(size_t)img * HO * HO + (size_t)m * HO + n] =
                        make_float2(v0, v1);
                }
            }
        }
    }
}

// ------------------------------------------------------------------ launch
extern "C" void kernel_launch(void* const* d_in, const int* in_sizes, int n_in,
                              void* d_out, int out_size) {
    (void)in_sizes; (void)n_in; (void)out_size;
    const float* x = (const float*)d_in[0];
    float* out = (float*)d_out;

    cudaFuncSetAttribute(fused_kernel,
                         cudaFuncAttributeMaxDynamicSharedMemorySize, 107584);

    init_kernel<<<49, 256>>>();
    fused_kernel<<<NIMG, 256, 107584>>>(x, out);
}

// round 11
// speedup vs baseline: 3.1580x; 1.0296x over previous
#include <cuda_runtime.h>
#include <cuda_fp16.h>
#include <cstdint>
#include <math.h>

// FLC pooling, fully fused: one CTA per image.
//   stage1: T[h][n]   = 0.5*x[h][2n] + sum_j x[h][2j+1] * R[n][j]   (h = 0..223)
//   stage2: out[m][n] = 0.5*Te[m][n] + sum_j R[m][j] * To[j][n]
//                       - (-1)^(m+n) * C_img / 224^2
//   C_img = sum_{a,b} (-1)^(a+b) x[2a+1][2b+1]
// T entirely in smem (To = odd h rows, Te = even h rows). fp16 operands,
// fp32 accum. Software-pipelined ldmatrix/MMA (double-buffered operands).

#define HO   112
#define NIMG 1024
#define PADB 240          // smem row stride bytes (120 fp16) -> conflict-free ldmatrix

__device__ __half g_R[HO * HO];

// ------------------------------------------------------------------ helpers
__device__ __forceinline__ uint32_t smem_u32(const void* p) {
    uint32_t a;
    asm("{ .reg .u64 t; cvta.to.shared.u64 t, %1; cvt.u32.u64 %0, t; }"
        : "=r"(a) : "l"(p));
    return a;
}
__device__ __forceinline__ void ldx4(uint32_t r[4], uint32_t a) {
    asm volatile("ldmatrix.sync.aligned.m8n8.x4.shared.b16 {%0,%1,%2,%3}, [%4];"
                 : "=r"(r[0]), "=r"(r[1]), "=r"(r[2]), "=r"(r[3]) : "r"(a));
}
__device__ __forceinline__ void ldx2(uint32_t r[2], uint32_t a) {
    asm volatile("ldmatrix.sync.aligned.m8n8.x2.shared.b16 {%0,%1}, [%2];"
                 : "=r"(r[0]), "=r"(r[1]) : "r"(a));
}
__device__ __forceinline__ void ldx4t(uint32_t r[4], uint32_t a) {
    asm volatile("ldmatrix.sync.aligned.m8n8.x4.trans.shared.b16 {%0,%1,%2,%3}, [%4];"
                 : "=r"(r[0]), "=r"(r[1]), "=r"(r[2]), "=r"(r[3]) : "r"(a));
}
__device__ __forceinline__ void ldx2t(uint32_t r[2], uint32_t a) {
    asm volatile("ldmatrix.sync.aligned.m8n8.x2.trans.shared.b16 {%0,%1}, [%2];"
                 : "=r"(r[0]), "=r"(r[1]) : "r"(a));
}
__device__ __forceinline__ void mma16816(float c[4], const uint32_t a[4],
                                         uint32_t b0, uint32_t b1) {
    asm volatile(
        "mma.sync.aligned.m16n8k16.row.col.f32.f16.f16.f32 "
        "{%0,%1,%2,%3}, {%4,%5,%6,%7}, {%8,%9}, {%0,%1,%2,%3};"
        : "+f"(c[0]), "+f"(c[1]), "+f"(c[2]), "+f"(c[3])
        : "r"(a[0]), "r"(a[1]), "r"(a[2]), "r"(a[3]), "r"(b0), "r"(b1));
}
__device__ __forceinline__ uint32_t pk2(float a, float b) {
    __half2 h = __floats2half2_rn(a, b);
    return *reinterpret_cast<uint32_t*>(&h);
}
__device__ __forceinline__ void sts64(uint32_t a, uint32_t x, uint32_t y) {
    asm volatile("st.shared.v2.b32 [%0], {%1,%2};" :: "r"(a), "r"(x), "r"(y) : "memory");
}

// normal-layout fetch (stage 1): B from R rows, A from x rows
#define S1_FETCH(S, ko) do {                                                       \
    uint32_t r_[4];                                                                \
    ldx4(r_, bA[0] + (ko)); b0##S[0]=r_[0]; b0##S[1]=r_[1]; b1##S[0]=r_[2]; b1##S[1]=r_[3]; \
    ldx4(r_, bA[1] + (ko)); b0##S[2]=r_[0]; b0##S[3]=r_[1]; b1##S[2]=r_[2]; b1##S[3]=r_[3]; \
    ldx4(r_, bA[2] + (ko)); b0##S[4]=r_[0]; b0##S[5]=r_[1]; b1##S[4]=r_[2]; b1##S[5]=r_[3]; \
    { uint32_t r2_[2]; ldx2(r2_, bA[3] + (ko)); b0##S[6]=r2_[0]; b1##S[6]=r2_[1]; } \
    ldx4(a0##S, aA0 + (ko)); ldx4(a1##S, aA1 + (ko));                              \
} while (0)

// transposed-B fetch (stage 2)
#define S2_FETCH(S, koA, koB) do {                                                 \
    uint32_t r_[4];                                                                \
    ldx4t(r_, bA[0] + (koB)); b0##S[0]=r_[0]; b1##S[0]=r_[1]; b0##S[1]=r_[2]; b1##S[1]=r_[3]; \
    ldx4t(r_, bA[1] + (koB)); b0##S[2]=r_[0]; b1##S[2]=r_[1]; b0##S[3]=r_[2]; b1##S[3]=r_[3]; \
    ldx4t(r_, bA[2] + (koB)); b0##S[4]=r_[0]; b1##S[4]=r_[1]; b0##S[5]=r_[2]; b1##S[5]=r_[3]; \
    { uint32_t r2_[2]; ldx2t(r2_, bA[3] + (koB)); b0##S[6]=r2_[0]; b1##S[6]=r2_[1]; } \
    ldx4(a0##S, aA0 + (koA)); ldx4(a1##S, aA1 + (koA));                            \
} while (0)

#define GEMM_MMA(S) do {                                                           \
    _Pragma("unroll")                                                              \
    for (int nt = 0; nt < 7; nt++) {                                               \
        mma16816(acc[0][nt], a0##S, b0##S[nt], b1##S[nt]);                         \
        mma16816(acc[1][nt], a1##S, b0##S[nt], b1##S[nt]);                         \
    }                                                                              \
} while (0)

// ------------------------------------------------------------------ init: R
__global__ void init_kernel() {
    int idx = blockIdx.x * blockDim.x + threadIdx.x;
    if (idx < HO * HO) {
        int n = idx / HO, j = idx % HO;
        int i2 = (n + 111 - j) % 112;
        int d = 2 * i2 + 1;
        float th = 3.14159265358979323846f * (float)d / 224.0f;
        float eps = (i2 & 1) ? -1.0f : 1.0f;
        float c = eps * (cosf(th) / sinf(th)) / 224.0f;
        g_R[idx] = __float2half_rn(c);
    }
}

// ------------------------------------------------------------------ fused
// CTA = one image. 1024 CTAs, 256 threads (8 warps, 4M x 2N warp tiling).
// smem: R 26880 | To 26880 | Te 26880 | A 26880 | red 64 = 107584 B
__global__ __launch_bounds__(256, 2) void fused_kernel(const float* __restrict__ x,
                                                       float* __restrict__ out) {
    extern __shared__ char sm[];
    const uint32_t SR = 0, STo = 26880, STe = 53760, SA = 80640, SRED = 107520;
    uint32_t sb = smem_u32(sm);
    int tid = threadIdx.x, wid = tid >> 5, lane = tid & 31;
    int img = blockIdx.x;

    // R -> smem (112 rows x 14 uint4, padded)
    {
        const uint4* rr = (const uint4*)g_R;
        for (int i = tid; i < 1568; i += 256) {
            int row = i / 14, q = i - row * 14;
            *(uint4*)(sm + SR + row * PADB + q * 16) = rr[i];
        }
    }

    // warp tiling (shared by both GEMMs)
    int wm = wid & 3, wn = wid >> 2, nbase = wn * 56;
    int mb0 = wm * 16, mb1 = (wm < 3) ? (mb0 + 64) : 96;

    float csum = 0.f;

    // ================= stage 1: two 112-row halves ======================
    #pragma unroll 1
    for (int half = 0; half < 2; half++) {
        int hbase = half * HO;
        if (half) __syncthreads();   // A reuse: all prior ldmatrix reads done

        // x half, odd cols -> fp16 A (8 floats/thread/iter); fused C-reduction
        {
            const float4* xr = (const float4*)(x + ((size_t)img * 224 + hbase) * 224);
            for (int i = tid; i < 3136; i += 256) {
                int r = i / 28, t2 = i - r * 28;
                const float4* p = xr + (size_t)r * 56 + 2 * t2;
                float4 v0 = p[0], v1 = p[1];
                sts64(sb + SA + r * PADB + 8 * t2,
                      pk2(v0.y, v0.w), pk2(v1.y, v1.w));
                int h = hbase + r;
                if (h & 1) {
                    float t = v0.y - v0.w + v1.y - v1.w;
                    csum += ((h >> 1) & 1) ? -t : t;
                }
            }
        }
        __syncthreads();

        uint32_t aoff = (uint32_t)((lane & 15) * PADB + (lane >> 4) * 16);
        uint32_t aA0 = sb + SA + mb0 * PADB + aoff;
        uint32_t aA1 = sb + SA + mb1 * PADB + aoff;
        uint32_t bA[4];
        #pragma unroll
        for (int p = 0; p < 3; p++) {
            int n = nbase + p * 16 + (lane & 7) + ((lane & 8) ? 8 : 0);
            int j = (lane & 16) ? 8 : 0;
            bA[p] = sb + SR + n * PADB + j * 2;
        }
        {
            int n = nbase + 48 + (lane & 7);
            int j = (lane & 8) ? 8 : 0;
            bA[3] = sb + SR + n * PADB + j * 2;
        }

        float acc[2][7][4];
        #pragma unroll
        for (int mt = 0; mt < 2; mt++)
            #pragma unroll
            for (int nt = 0; nt < 7; nt++)
                #pragma unroll
                for (int q = 0; q < 4; q++) acc[mt][nt][q] = 0.f;

        // software-pipelined k-loop (7 chunks, double-buffered operands)
        uint32_t b0A[7], b1A[7], a0A[4], a1A[4];
        uint32_t b0B[7], b1B[7], a0B[4], a1B[4];
        S1_FETCH(A, 0);
        #pragma unroll
        for (int kk = 0; kk < 7; kk++) {
            uint32_t kon = (uint32_t)(kk + 1) * 32;
            if (kk & 1) {
                if (kk < 6) S1_FETCH(A, kon);
                GEMM_MMA(B);
            } else {
                if (kk < 6) S1_FETCH(B, kon);
                GEMM_MMA(A);
            }
        }

        // epilogue: + 0.5*x[h][2n] (one float4 covers both cols), -> To/Te smem
        const float* xim = x + ((size_t)img * 224 + hbase) * 224;
        #pragma unroll
        for (int mt = 0; mt < 2; mt++) {
            if (mt == 1 && wm == 3) break;
            int mb = mt ? mb1 : mb0;
            int rlo = mb + (lane >> 2), rhi = rlo + 8;
            #pragma unroll
            for (int nt = 0; nt < 7; nt++) {
                int n = nbase + nt * 8 + 2 * (lane & 3);
                float4 e0 = __ldg((const float4*)(xim + (size_t)rlo * 224 + 2 * n));
                float4 e1 = __ldg((const float4*)(xim + (size_t)rhi * 224 + 2 * n));
                float v0 = acc[mt][nt][0] + 0.5f * e0.x;
                float v1 = acc[mt][nt][1] + 0.5f * e0.z;
                float v2 = acc[mt][nt][2] + 0.5f * e1.x;
                float v3 = acc[mt][nt][3] + 0.5f * e1.z;
                #pragma unroll
                for (int hf = 0; hf < 2; hf++) {
                    int h = hbase + (hf ? rhi : rlo);
                    uint32_t pv = hf ? pk2(v2, v3) : pk2(v0, v1);
                    uint32_t off = (uint32_t)((h >> 1) * PADB + 2 * n);
                    if (h & 1) *(uint32_t*)(sm + STo + off) = pv;
                    else       *(uint32_t*)(sm + STe + off) = pv;
                }
            }
        }
    }

    // C reduction -> corr (intra-CTA only)
    #pragma unroll
    for (int o = 16; o; o >>= 1) csum += __shfl_down_sync(0xffffffffu, csum, o);
    if (lane == 0) ((float*)(sm + SRED))[wid] = csum;
    __syncthreads();   // also publishes all To/Te writes
    float corr;
    {
        float s = 0.f;
        #pragma unroll
        for (int i = 0; i < 8; i++) s += ((float*)(sm + SRED))[i];
        corr = s * (1.0f / 50176.0f);
    }

    // ================= stage 2 =========================================
    {
        uint32_t aoff = (uint32_t)((lane & 15) * PADB + (lane >> 4) * 16);
        uint32_t aA0 = sb + SR + mb0 * PADB + aoff;
        uint32_t aA1 = sb + SR + mb1 * PADB + aoff;
        uint32_t bA[4];
        #pragma unroll
        for (int p = 0; p < 3; p++) {
            int j = (lane & 7) + ((lane & 8) ? 8 : 0);
            int n = nbase + p * 16 + ((lane & 16) ? 8 : 0);
            bA[p] = sb + STo + j * PADB + n * 2;
        }
        {
            int j = lane & 15;
            bA[3] = sb + STo + j * PADB + (nbase + 48) * 2;
        }

        float acc[2][7][4];
        #pragma unroll
        for (int mt = 0; mt < 2; mt++)
            #pragma unroll
            for (int nt = 0; nt < 7; nt++)
                #pragma unroll
                for (int q = 0; q < 4; q++) acc[mt][nt][q] = 0.f;

        uint32_t b0A[7], b1A[7], a0A[4], a1A[4];
        uint32_t b0B[7], b1B[7], a0B[4], a1B[4];
        S2_FETCH(A, 0, 0);
        #pragma unroll
        for (int kk = 0; kk < 7; kk++) {
            uint32_t koAn = (uint32_t)(kk + 1) * 32;
            uint32_t koBn = (uint32_t)(kk + 1) * 16 * PADB;
            if (kk & 1) {
                if (kk < 6) S2_FETCH(A, koAn, koBn);
                GEMM_MMA(B);
            } else {
                if (kk < 6) S2_FETCH(B, koAn, koBn);
                GEMM_MMA(A);
            }
        }

        // epilogue: + 0.5*Te[m][n] - sign*corr, write fp32 out
        #pragma unroll
        for (int mt = 0; mt < 2; mt++) {
            if (mt == 1 && wm == 3) break;
            int mb = mt ? mb1 : mb0;
            int mlo = mb + (lane >> 2), mhi = mlo + 8;
            #pragma unroll
            for (int nt = 0; nt < 7; nt++) {
                int n = nbase + nt * 8 + 2 * (lane & 3);
                #pragma unroll
                for (int hf = 0; hf < 2; hf++) {
                    int m = hf ? mhi : mlo;
                    uint32_t tp = *(const uint32_t*)(sm + STe + m * PADB + 2 * n);
                    __half2 th = *reinterpret_cast<__half2*>(&tp);
                    float v0 = acc[mt][nt][hf ? 2 : 0] + 0.5f * __half2float(th.x);
                    float v1 = acc[mt][nt][hf ? 3 : 1] + 0.5f * __half2float(th.y);
                    v0 -= ((m + n) & 1) ? -corr : corr;
                    v1 -= ((m + n + 1) & 1) ? -corr : corr;
                    *(float2*)&out[(size_t)img * HO * HO + (size_t)m * HO + n] =
                        make_float2(v0, v1);
                }
            }
        }
    }
}

// ------------------------------------------------------------------ launch
extern "C" void kernel_launch(void* const* d_in, const int* in_sizes, int n_in,
                              void* d_out, int out_size) {
    (void)in_sizes; (void)n_in; (void)out_size;
    const float* x = (const float*)d_in[0];
    float* out = (float*)d_out;

    cudaFuncSetAttribute(fused_kernel,
                         cudaFuncAttributeMaxDynamicSharedMemorySize, 107584);

    init_kernel<<<49, 256>>>();
    fused_kernel<<<NIMG, 256, 107584>>>(x, out);
}

// round 12
// speedup vs baseline: 4.5180x; 1.4307x over previous
#include <cuda_runtime.h>
#include <cuda_fp16.h>
#include <cstdint>
#include <math.h>

// FLC pooling, fully fused, circulant-strip edition. One CTA per image.
//   stage1: T[h][n]   = 0.5*x[h][2n] + sum_j x[h][2j+1] * R[n][j]
//   stage2: out[m][n] = 0.5*Te[m][n] + sum_j R[m][j] * To[j][n] - (-1)^(m+n)*C/224^2
// R[n][j] = rodd[(n-j-1) mod 112] is CIRCULANT; with j' = 111-j both GEMMs read
// coefficients as v2[idx] from a 448B strip (v2[t] = rodd[t mod 112]).
// B frags (s1) and A frags (s2) come from 4B smem loads; x-even columns are
// stashed in smem (Aev) during the load phase (no global re-read in epilogue).

#define HO   112
#define NIMG 1024
#define PADB 240          // smem row stride bytes -> conflict-free ldmatrix

__device__ __half g_strip[448];   // [0..223]=v2[t]; [224+i]=v2[i+1] (parity copy)

// ------------------------------------------------------------------ helpers
__device__ __forceinline__ uint32_t smem_u32(const void* p) {
    uint32_t a;
    asm("{ .reg .u64 t; cvta.to.shared.u64 t, %1; cvt.u32.u64 %0, t; }"
        : "=r"(a) : "l"(p));
    return a;
}
__device__ __forceinline__ void ldx4(uint32_t r[4], uint32_t a) {
    asm volatile("ldmatrix.sync.aligned.m8n8.x4.shared.b16 {%0,%1,%2,%3}, [%4];"
                 : "=r"(r[0]), "=r"(r[1]), "=r"(r[2]), "=r"(r[3]) : "r"(a));
}
__device__ __forceinline__ void ldx4t(uint32_t r[4], uint32_t a) {
    asm volatile("ldmatrix.sync.aligned.m8n8.x4.trans.shared.b16 {%0,%1,%2,%3}, [%4];"
                 : "=r"(r[0]), "=r"(r[1]), "=r"(r[2]), "=r"(r[3]) : "r"(a));
}
__device__ __forceinline__ void ldx2t(uint32_t r[2], uint32_t a) {
    asm volatile("ldmatrix.sync.aligned.m8n8.x2.trans.shared.b16 {%0,%1}, [%2];"
                 : "=r"(r[0]), "=r"(r[1]) : "r"(a));
}
__device__ __forceinline__ void mma16816(float c[4], const uint32_t a[4],
                                         uint32_t b0, uint32_t b1) {
    asm volatile(
        "mma.sync.aligned.m16n8k16.row.col.f32.f16.f16.f32 "
        "{%0,%1,%2,%3}, {%4,%5,%6,%7}, {%8,%9}, {%0,%1,%2,%3};"
        : "+f"(c[0]), "+f"(c[1]), "+f"(c[2]), "+f"(c[3])
        : "r"(a[0]), "r"(a[1]), "r"(a[2]), "r"(a[3]), "r"(b0), "r"(b1));
}
__device__ __forceinline__ uint32_t pk2(float a, float b) {
    __half2 h = __floats2half2_rn(a, b);
    return *reinterpret_cast<uint32_t*>(&h);
}
__device__ __forceinline__ void sts64(uint32_t a, uint32_t x, uint32_t y) {
    asm volatile("st.shared.v2.b32 [%0], {%1,%2};" :: "r"(a), "r"(x), "r"(y) : "memory");
}

// transposed-B fetch for stage 2 (To' rows = k dim)
#define S2_FETCHB(S, koB) do {                                                     \
    uint32_t r_[4];                                                                \
    ldx4t(r_, bA[0] + (koB)); b0##S[0]=r_[0]; b1##S[0]=r_[1]; b0##S[1]=r_[2]; b1##S[1]=r_[3]; \
    ldx4t(r_, bA[1] + (koB)); b0##S[2]=r_[0]; b1##S[2]=r_[1]; b0##S[3]=r_[2]; b1##S[3]=r_[3]; \
    ldx4t(r_, bA[2] + (koB)); b0##S[4]=r_[0]; b1##S[4]=r_[1]; b0##S[5]=r_[2]; b1##S[5]=r_[3]; \
    { uint32_t r2_[2]; ldx2t(r2_, bA[3] + (koB)); b0##S[6]=r2_[0]; b1##S[6]=r2_[1]; } \
} while (0)

// ------------------------------------------------------------------ init
__global__ void init_kernel() {
    int idx = blockIdx.x * blockDim.x + threadIdx.x;
    if (idx < 448) {
        int t = (idx < 224) ? idx : (idx - 224 + 1);   // parity-shifted copy
        float c = 0.f;
        if (t < 224) {
            int i2 = t % 112;
            int d = 2 * i2 + 1;
            float th = 3.14159265358979323846f * (float)d / 224.0f;
            float eps = (i2 & 1) ? -1.0f : 1.0f;
            c = eps * (cosf(th) / sinf(th)) / 224.0f;
        }
        g_strip[idx] = __float2half_rn(c);
    }
}

// ------------------------------------------------------------------ fused
// smem: A 26880 | Aev 26880 | To' 26880 | Te 26880 | strip 896 | red 32
__global__ __launch_bounds__(256, 2) void fused_kernel(const float* __restrict__ x,
                                                       float* __restrict__ out) {
    extern __shared__ char sm[];
    const uint32_t SA = 0, SAE = 26880, STo = 53760, STe = 80640,
                   SSTRIP = 107520, SRED = 108416;
    uint32_t sb = smem_u32(sm);
    int tid = threadIdx.x, wid = tid >> 5, lane = tid & 31;
    int img = blockIdx.x;

    // strip -> smem (224 words)
    {
        const uint32_t* gs = (const uint32_t*)g_strip;
        for (int i = tid; i < 224; i += 256)
            *(uint32_t*)(sm + SSTRIP + i * 4) = gs[i];
    }

    // warp tiling (shared by both GEMMs)
    int wm = wid & 3, wn = wid >> 2, nbase = wn * 56;
    int mb0 = wm * 16, mb1 = (wm < 3) ? (mb0 + 64) : 96;

    const uint32_t* stripw =
        (const uint32_t*)(sm + SSTRIP + (((lane >> 2) & 1) ? 448 : 0));
    int lterm = (lane >> 2) + ((lane & 3) << 1);   // per-lane frag offset

    float csum = 0.f;

    // ================= stage 1: two 112-row halves ======================
    #pragma unroll 1
    for (int half = 0; half < 2; half++) {
        int hbase = half * HO;
        if (half) __syncthreads();   // A/Aev reuse barrier

        // x half -> odds reversed into A (j' = 111 - j), evens into Aev
        {
            const float4* xr = (const float4*)(x + ((size_t)img * 224 + hbase) * 224);
            for (int i = tid; i < 3136; i += 256) {
                int r = i / 28, t2 = i - r * 28;
                const float4* p = xr + (size_t)r * 56 + 2 * t2;
                float4 v0 = p[0], v1 = p[1];
                // A'[r][108-4t2 .. 111-4t2] = (x[8t2+7], x[8t2+5], x[8t2+3], x[8t2+1])
                sts64(sb + SA + r * PADB + (216 - 8 * t2),
                      pk2(v1.w, v1.y), pk2(v0.w, v0.y));
                // Aev[r][4t2 .. 4t2+3] = (x[8t2], x[8t2+2], x[8t2+4], x[8t2+6])
                sts64(sb + SAE + r * PADB + 8 * t2,
                      pk2(v0.x, v0.z), pk2(v1.x, v1.z));
                int h = hbase + r;
                if (h & 1) {
                    float t = v0.y - v0.w + v1.y - v1.w;
                    csum += ((h >> 1) & 1) ? -t : t;
                }
            }
        }
        __syncthreads();

        uint32_t aoff = (uint32_t)((lane & 15) * PADB + (lane >> 4) * 16);
        uint32_t aA0 = sb + SA + mb0 * PADB + aoff;
        uint32_t aA1 = sb + SA + mb1 * PADB + aoff;

        float acc[2][7][4];
        #pragma unroll
        for (int mt = 0; mt < 2; mt++)
            #pragma unroll
            for (int nt = 0; nt < 7; nt++)
                #pragma unroll
                for (int q = 0; q < 4; q++) acc[mt][nt][q] = 0.f;

        int wq = (nbase + lterm) >> 1;   // strip word base for B frags
        uint32_t a0X[4], a1X[4], a0Y[4], a1Y[4];
        ldx4(a0X, aA0); ldx4(a1X, aA1);
        #pragma unroll
        for (int kk = 0; kk < 7; kk++) {
            // B frags from circulant strip: L[q] = (v2[w+8q], v2[w+8q+1])
            uint32_t L[8];
            #pragma unroll
            for (int q = 0; q < 8; q++) L[q] = stripw[wq + 8 * kk + 4 * q];
            if (kk < 6) {
                uint32_t ko = (uint32_t)(kk + 1) * 32;
                if (kk & 1) { ldx4(a0X, aA0 + ko); ldx4(a1X, aA1 + ko); }
                else        { ldx4(a0Y, aA0 + ko); ldx4(a1Y, aA1 + ko); }
            }
            const uint32_t* a0c = (kk & 1) ? a0Y : a0X;
            const uint32_t* a1c = (kk & 1) ? a1Y : a1X;
            #pragma unroll
            for (int nt = 0; nt < 7; nt++) {
                mma16816(acc[0][nt], a0c, L[nt], L[nt + 1]);
                mma16816(acc[1][nt], a1c, L[nt], L[nt + 1]);
            }
        }

        // epilogue: + 0.5*x[h][2n] from Aev (smem), route to To'(reversed)/Te
        #pragma unroll
        for (int mt = 0; mt < 2; mt++) {
            if (mt == 1 && wm == 3) break;
            int mb = mt ? mb1 : mb0;
            int rlo = mb + (lane >> 2), rhi = rlo + 8;
            #pragma unroll
            for (int nt = 0; nt < 7; nt++) {
                int n = nbase + nt * 8 + 2 * (lane & 3);
                uint32_t e0 = *(const uint32_t*)(sm + SAE + rlo * PADB + n * 2);
                uint32_t e1 = *(const uint32_t*)(sm + SAE + rhi * PADB + n * 2);
                __half2 h0 = *reinterpret_cast<__half2*>(&e0);
                __half2 h1 = *reinterpret_cast<__half2*>(&e1);
                float v0 = acc[mt][nt][0] + 0.5f * __half2float(h0.x);
                float v1 = acc[mt][nt][1] + 0.5f * __half2float(h0.y);
                float v2 = acc[mt][nt][2] + 0.5f * __half2float(h1.x);
                float v3 = acc[mt][nt][3] + 0.5f * __half2float(h1.y);
                #pragma unroll
                for (int hf = 0; hf < 2; hf++) {
                    int h = hbase + (hf ? rhi : rlo);
                    uint32_t pv = hf ? pk2(v2, v3) : pk2(v0, v1);
                    int q = h >> 1;
                    if (h & 1)
                        *(uint32_t*)(sm + STo + (111 - q) * PADB + 2 * n) = pv;
                    else
                        *(uint32_t*)(sm + STe + q * PADB + 2 * n) = pv;
                }
            }
        }
    }

    // C reduction -> corr (intra-CTA)
    #pragma unroll
    for (int o = 16; o; o >>= 1) csum += __shfl_down_sync(0xffffffffu, csum, o);
    if (lane == 0) ((float*)(sm + SRED))[wid] = csum;
    __syncthreads();   // also publishes To'/Te
    float corr;
    {
        float s = 0.f;
        #pragma unroll
        for (int i = 0; i < 8; i++) s += ((float*)(sm + SRED))[i];
        corr = s * (1.0f / 50176.0f);
    }

    // ================= stage 2 =========================================
    {
        uint32_t bA[4];
        #pragma unroll
        for (int p = 0; p < 3; p++) {
            int j = (lane & 7) + ((lane & 8) ? 8 : 0);
            int n = nbase + p * 16 + ((lane & 16) ? 8 : 0);
            bA[p] = sb + STo + j * PADB + n * 2;
        }
        {
            int j = lane & 15;
            bA[3] = sb + STo + j * PADB + (nbase + 48) * 2;
        }

        float acc[2][7][4];
        #pragma unroll
        for (int mt = 0; mt < 2; mt++)
            #pragma unroll
            for (int nt = 0; nt < 7; nt++)
                #pragma unroll
                for (int q = 0; q < 4; q++) acc[mt][nt][q] = 0.f;

        int wq0 = (mb0 + lterm) >> 1;          // strip word base, m-tile 0
        int wq1 = wq0 + ((mb1 - mb0) >> 1);    // m-tile 1

        uint32_t b0X[7], b1X[7], b0Y[7], b1Y[7];
        S2_FETCHB(X, 0);
        #pragma unroll
        for (int kk = 0; kk < 7; kk++) {
            // A frags from strip (circulant: a2 == a1; values v2[w], v2[w+8], v2[w+16])
            uint32_t A0a = stripw[wq0 + 8 * kk];
            uint32_t A1a = stripw[wq0 + 8 * kk + 4];
            uint32_t A3a = stripw[wq0 + 8 * kk + 8];
            uint32_t A0b = stripw[wq1 + 8 * kk];
            uint32_t A1b = stripw[wq1 + 8 * kk + 4];
            uint32_t A3b = stripw[wq1 + 8 * kk + 8];
            uint32_t am0[4] = {A0a, A1a, A1a, A3a};
            uint32_t am1[4] = {A0b, A1b, A1b, A3b};
            if (kk < 6) {
                uint32_t koB = (uint32_t)(kk + 1) * 16 * PADB;
                if (kk & 1) { S2_FETCHB(X, koB); }
                else        { S2_FETCHB(Y, koB); }
            }
            const uint32_t* b0c = (kk & 1) ? b0Y : b0X;
            const uint32_t* b1c = (kk & 1) ? b1Y : b1X;
            #pragma unroll
            for (int nt = 0; nt < 7; nt++) {
                mma16816(acc[0][nt], am0, b0c[nt], b1c[nt]);
                mma16816(acc[1][nt], am1, b0c[nt], b1c[nt]);
            }
        }

        // epilogue: + 0.5*Te[m][n] - sign*corr, write fp32 out
        #pragma unroll
        for (int mt = 0; mt < 2; mt++) {
            if (mt == 1 && wm == 3) break;
            int mb = mt ? mb1 : mb0;
            int mlo = mb + (lane >> 2), mhi = mlo + 8;
            #pragma unroll
            for (int nt = 0; nt < 7; nt++) {
                int n = nbase + nt * 8 + 2 * (lane & 3);
                #pragma unroll
                for (int hf = 0; hf < 2; hf++) {
                    int m = hf ? mhi : mlo;
                    uint32_t tp = *(const uint32_t*)(sm + STe + m * PADB + 2 * n);
                    __half2 th = *reinterpret_cast<__half2*>(&tp);
                    float v0 = acc[mt][nt][hf ? 2 : 0] + 0.5f * __half2float(th.x);
                    float v1 = acc[mt][nt][hf ? 3 : 1] + 0.5f * __half2float(th.y);
                    v0 -= ((m + n) & 1) ? -corr : corr;
                    v1 -= ((m + n + 1) & 1) ? -corr : corr;
                    *(float2*)&out[(size_t)img * HO * HO + (size_t)m * HO + n] =
                        make_float2(v0, v1);
                }
            }
        }
    }
}

// ------------------------------------------------------------------ launch
extern "C" void kernel_launch(void* const* d_in, const int* in_sizes, int n_in,
                              void* d_out, int out_size) {
    (void)in_sizes; (void)n_in; (void)out_size;
    const float* x = (const float*)d_in[0];
    float* out = (float*)d_out;

    cudaFuncSetAttribute(fused_kernel,
                         cudaFuncAttributeMaxDynamicSharedMemorySize, 108448);

    init_kernel<<<2, 256>>>();
    fused_kernel<<<NIMG, 256, 108448>>>(x, out);
}